// round 14
// baseline (speedup 1.0000x reference)
#include <cuda_runtime.h>
#include <cuda_bf16.h>

#define KNB 32
#define INVALID_KEY 0xFFFFFFFFFFFFFFFFull
#define FULLMASK 0xFFFFFFFFu
// exact d2 threshold: dist<=5.0 with dist=__fsqrt_rn(d2)  <=>  d2 <= 25+2^-19
#define D2_THRESH_BITS 0x41C80001u
#define CAP 768   // smem staging capacity (atoms); fallback to global if exceeded

typedef unsigned long long u64;

// XLA-matching sum of squares: rn(rn(rn(x^2)+rn(y^2))+rn(z^2)), NO fma fusion
__device__ __forceinline__ float sumsq_xla(float x, float y, float z) {
    return __fadd_rn(__fadd_rn(__fmul_rn(x, x), __fmul_rn(y, y)), __fmul_rn(z, z));
}

__device__ __forceinline__ u64 shfl_xor64(u64 v, int m) { return __shfl_xor_sync(FULLMASK, v, m); }

// dual warp-parallel 32-ary search over the SAME molecule id b:
//   LO = first idx with batch[idx] >= b ; HI = first idx with batch[idx] > b
__device__ __forceinline__ int2 warp_bound_dual(const int* __restrict__ batch, int N,
                                                int b, int lane) {
    int l0 = 0, w0 = N, l1 = 0, w1 = N;
    while (w0 > 0 || w1 > 0) {
        int step0 = (w0 + 31) >> 5;
        int step1 = (w1 + 31) >> 5;
        int off0 = lane * step0;
        int off1 = lane * step1;
        bool in0 = (w0 > 0) && (off0 < w0);
        bool in1 = (w1 > 0) && (off1 < w1);
        int m0 = l0 + (in0 ? off0 : 0);
        int m1 = l1 + (in1 ? off1 : 0);
        int v0 = batch[m0];
        int v1 = batch[m1];
        unsigned bal0 = __ballot_sync(FULLMASK, in0 && (v0 < b));
        unsigned bal1 = __ballot_sync(FULLMASK, in1 && (v1 <= b));
        if (w0 > 0) {
            int c = __popc(bal0);
            if (c == 0) w0 = 0;
            else {
                int newl = l0 + (c - 1) * step0 + 1;
                int ub = (c * step0 < w0) ? (l0 + c * step0) : (l0 + w0);
                w0 = ub - newl; l0 = newl;
            }
        }
        if (w1 > 0) {
            int c = __popc(bal1);
            if (c == 0) w1 = 0;
            else {
                int newl = l1 + (c - 1) * step1 + 1;
                int ub = (c * step1 < w1) ? (l1 + c * step1) : (l1 + w1);
                w1 = ub - newl; l1 = newl;
            }
        }
    }
    return make_int2(l0, l1);
}

// full bitonic sort of 32 keys, ascending by lane
__device__ __forceinline__ void bitonic_sort32(u64& v, int lane) {
#pragma unroll
    for (int k = 2; k <= 32; k <<= 1) {
#pragma unroll
        for (int j = k >> 1; j > 0; j >>= 1) {
            u64 o = shfl_xor64(v, j);
            bool takeMin = (((lane & j) == 0) == ((lane & k) == 0));
            if ((o < v) == takeMin) v = o;
        }
    }
}

// two independent sorts interleaved (2x ILP on the shfl chain)
__device__ __forceinline__ void bitonic_sort32_pair(u64& a, u64& b, int lane) {
#pragma unroll
    for (int k = 2; k <= 32; k <<= 1) {
#pragma unroll
        for (int j = k >> 1; j > 0; j >>= 1) {
            u64 oa = shfl_xor64(a, j);
            u64 ob = shfl_xor64(b, j);
            bool takeMin = (((lane & j) == 0) == ((lane & k) == 0));
            if ((oa < a) == takeMin) a = oa;
            if ((ob < b) == takeMin) b = ob;
        }
    }
}

// bitonic merge (input bitonic), ascending by lane
__device__ __forceinline__ void bitonic_merge32(u64& v, int lane) {
#pragma unroll
    for (int j = 16; j > 0; j >>= 1) {
        u64 o = shfl_xor64(v, j);
        bool takeMin = ((lane & j) == 0);
        if ((o < v) == takeMin) v = o;
    }
}

// insert key k into sorted-ascending L (drops old max). No-op if k >= L[31].
__device__ __forceinline__ void warp_insert(u64& L, u64 k, int lane) {
    unsigned mlt = __ballot_sync(FULLMASK, L < k);
    int p = __popc(mlt);
    u64 Ls = __shfl_up_sync(FULLMASK, L, 1);
    if (lane >= p) L = (lane == p) ? k : Ls;
}

// rare mid-loop flush: fold the 64-slot smem buffer into L, reset buffer
__device__ __forceinline__ void flush_smem(u64& L, bool& first, int& cnt,
                                           u64* buf, int lane) {
    __syncwarp();
    u64 A = buf[lane];
    u64 B = buf[32 + lane];
    bitonic_sort32_pair(A, B, lane);
    u64 brev = shfl_xor64(B, 31);
    u64 C = (A < brev) ? A : brev;
    bitonic_merge32(C, lane);
    if (first) { L = C; first = false; }
    else {
        u64 crev = shfl_xor64(C, 31);
        L = (L < crev) ? L : crev;
        bitonic_merge32(L, lane);
    }
    buf[lane] = INVALID_KEY;
    buf[32 + lane] = INVALID_KEY;
    __syncwarp();
    cnt = 0;
}

// rare final path when a mid-loop flush happened
__device__ __forceinline__ void finalize_merge(u64& L, int cnt, u64 A,
                                               const u64* buf, int lane) {
    if (cnt == 0) return;
    u64 arev = shfl_xor64(A, 31);
    L = (L < arev) ? L : arev;
    bitonic_merge32(L, lane);
    if (cnt > 32) {
        u64 B = buf[32 + lane];
        bitonic_sort32(B, lane);
        u64 brev = shfl_xor64(B, 31);
        L = (L < brev) ? L : brev;
        bitonic_merge32(L, lane);
    }
}

__global__ void __launch_bounds__(128)
radius_graph_kernel(const float* __restrict__ pos,
                    const int* __restrict__ batch,
                    float* __restrict__ out,
                    int N) {
    __shared__ float4 spos[CAP];
    __shared__ u64 sbuf[4][64];
    __shared__ int sLO[4], sHI[4];

    const int wb = (int)(threadIdx.x >> 5);
    const int lane = threadIdx.x & 31;
    const int i = (int)blockIdx.x * 4 + wb;
    const bool valid_atom = (i < N);
    const int nk = N * KNB;
    const float D2T = __uint_as_float(D2_THRESH_BITS);
    const unsigned lmlt = (1u << lane) - 1u;

    sbuf[wb][lane] = INVALID_KEY;
    sbuf[wb][32 + lane] = INVALID_KEY;

    float xi = 0.0f, yi = 0.0f, zi = 0.0f, sqi = 0.0f;
    int b = 0;
    int LO = 0, HI = 0;
    if (valid_atom) {
        xi = pos[3 * i + 0]; yi = pos[3 * i + 1]; zi = pos[3 * i + 2];
        sqi = sumsq_xla(xi, yi, zi);
        b = batch[i];
        int2 bounds = warp_bound_dual(batch, N, b, lane);
        LO = bounds.x; HI = bounds.y;
    }
    if (lane == 0) { sLO[wb] = LO; sHI[wb] = HI; }
    __syncthreads();

    // block span: first warp always valid; last valid warp gives HIb
    const int nvw = (N - (int)blockIdx.x * 4 < 4) ? (N - (int)blockIdx.x * 4) : 4;
    const int LOb = sLO[0];
    const int HIb = sHI[nvw - 1];
    const int range = HIb - LOb;
    const bool useSmem = (range <= CAP);

    if (useSmem) {
        for (int k = threadIdx.x; k < range; k += 128) {
            int g = LOb + k;
            float x = pos[3 * g + 0];
            float y = pos[3 * g + 1];
            float z = pos[3 * g + 2];
            spos[k] = make_float4(x, y, z, sumsq_xla(x, y, z));
        }
    }
    __syncthreads();

    u64 L = INVALID_KEY;
    int cnt = 0;
    bool first = true;

    if (valid_atom) {
        const int per = (HI - LO + 31) >> 5;
        for (int t = 0; t < per; t++) {
            int j = LO + lane + (t << 5);
            u64 key = INVALID_KEY;
            if (j < HI && j != i) {
                float xj, yj, zj, sqj;
                if (useSmem) {
                    float4 p = spos[j - LOb];
                    xj = p.x; yj = p.y; zj = p.z; sqj = p.w;
                } else {
                    xj = pos[3 * j + 0]; yj = pos[3 * j + 1]; zj = pos[3 * j + 2];
                    sqj = sumsq_xla(xj, yj, zj);
                }
                float dot = __fmaf_rn(zi, zj, __fmaf_rn(yi, yj, __fmul_rn(xi, xj)));
                float d2 = __fsub_rn(__fadd_rn(sqi, sqj), __fmul_rn(2.0f, dot));
                if (d2 <= D2T) {   // exact equivalent of dist<=5.0
                    float dist = __fsqrt_rn(fmaxf(d2, 0.0f));
                    key = (((u64)__float_as_uint(dist)) << 32) | (unsigned int)j;
                }
            }
            unsigned bal = __ballot_sync(FULLMASK, key != INVALID_KEY);
            if (bal) {
                int nv = __popc(bal);
                if (cnt + nv > 64) flush_smem(L, first, cnt, &sbuf[wb][0], lane);
                int r = __popc(bal & lmlt);
                if (key != INVALID_KEY) sbuf[wb][cnt + r] = key;
                cnt += nv;
            }
        }

        __syncwarp();
        u64 A = sbuf[wb][lane];
        bitonic_sort32(A, lane);

        if (first) {
            if (cnt > 0) L = A;
            int m = cnt > 32 ? cnt - 32 : 0;
            for (int idx = 0; idx < m; idx++)
                warp_insert(L, sbuf[wb][32 + idx], lane);
        } else {
            finalize_merge(L, cnt, A, &sbuf[wb][0], lane);
        }

        // lane k owns output slot k: k-th nearest neighbor (exact top_k order)
        const bool valid = (L != INVALID_KEY);
        const int jd = valid ? (int)(unsigned int)(L & 0xFFFFFFFFull) : i;
        const int e = i * KNB + lane;
        float vx = 0.0f, vy = 0.0f, vz = 0.0f;
        if (valid) {
            if (useSmem) {
                float4 p = spos[jd - LOb];   // jd in [LO,HI) subset of [LOb,HIb)
                vx = __fsub_rn(p.x, xi);
                vy = __fsub_rn(p.y, yi);
                vz = __fsub_rn(p.z, zi);
            } else {
                vx = __fsub_rn(pos[3 * jd + 0], xi);
                vy = __fsub_rn(pos[3 * jd + 1], yi);
                vz = __fsub_rn(pos[3 * jd + 2], zi);
            }
        }
        out[e]                  = (float)i;            // src
        out[nk + e]             = (float)jd;           // dst
        out[2 * nk + 3 * e + 0] = vx;                  // edge_vec
        out[2 * nk + 3 * e + 1] = vy;
        out[2 * nk + 3 * e + 2] = vz;
        out[5 * nk + e]         = valid ? 1.0f : 0.0f; // mask
    }
}

extern "C" void kernel_launch(void* const* d_in, const int* in_sizes, int n_in,
                              void* d_out, int out_size) {
    const float* pos = (const float*)d_in[0];
    const int* batch = (const int*)d_in[1];
    float* out = (float*)d_out;
    int N = in_sizes[1];            // batch has one entry per atom
    (void)n_in; (void)out_size;

    int blocks = (N + 3) / 4;       // one atom per warp, 4 warps per block
    radius_graph_kernel<<<blocks, 128>>>(pos, batch, out, N);
}

// round 15
// speedup vs baseline: 1.1142x; 1.1142x over previous
#include <cuda_runtime.h>
#include <cuda_bf16.h>

#define KNB 32
#define INVALID_KEY 0xFFFFFFFFFFFFFFFFull
#define FULLMASK 0xFFFFFFFFu
// exact d2 threshold: dist<=5.0 with dist=__fsqrt_rn(d2)  <=>  d2 <= 25+2^-19
#define D2_THRESH_BITS 0x41C80001u
#define PDEPTH 8      // lane-private slots; covers molecules up to 256 atoms
#define COMPCAP 288   // compacted buffer (256 max keys + 32 pad for chunk reads)

typedef unsigned long long u64;

// XLA-matching sum of squares: rn(rn(rn(x^2)+rn(y^2))+rn(z^2)), NO fma fusion
__device__ __forceinline__ float sumsq_xla(float x, float y, float z) {
    return __fadd_rn(__fadd_rn(__fmul_rn(x, x), __fmul_rn(y, y)), __fmul_rn(z, z));
}

__device__ __forceinline__ u64 shfl_xor64(u64 v, int m) { return __shfl_xor_sync(FULLMASK, v, m); }

// dual warp-parallel 32-ary search over the SAME molecule id b:
//   LO = first idx with batch[idx] >= b ; HI = first idx with batch[idx] > b
__device__ __forceinline__ int2 warp_bound_dual(const int* __restrict__ batch, int N,
                                                int b, int lane) {
    int l0 = 0, w0 = N, l1 = 0, w1 = N;
    while (w0 > 0 || w1 > 0) {
        int step0 = (w0 + 31) >> 5;
        int step1 = (w1 + 31) >> 5;
        int off0 = lane * step0;
        int off1 = lane * step1;
        bool in0 = (w0 > 0) && (off0 < w0);
        bool in1 = (w1 > 0) && (off1 < w1);
        int m0 = l0 + (in0 ? off0 : 0);
        int m1 = l1 + (in1 ? off1 : 0);
        int v0 = batch[m0];
        int v1 = batch[m1];
        unsigned bal0 = __ballot_sync(FULLMASK, in0 && (v0 < b));
        unsigned bal1 = __ballot_sync(FULLMASK, in1 && (v1 <= b));
        if (w0 > 0) {
            int c = __popc(bal0);
            if (c == 0) w0 = 0;
            else {
                int newl = l0 + (c - 1) * step0 + 1;
                int ub = (c * step0 < w0) ? (l0 + c * step0) : (l0 + w0);
                w0 = ub - newl; l0 = newl;
            }
        }
        if (w1 > 0) {
            int c = __popc(bal1);
            if (c == 0) w1 = 0;
            else {
                int newl = l1 + (c - 1) * step1 + 1;
                int ub = (c * step1 < w1) ? (l1 + c * step1) : (l1 + w1);
                w1 = ub - newl; l1 = newl;
            }
        }
    }
    return make_int2(l0, l1);
}

// full bitonic sort of 32 keys, ascending by lane
__device__ __forceinline__ void bitonic_sort32(u64& v, int lane) {
#pragma unroll
    for (int k = 2; k <= 32; k <<= 1) {
#pragma unroll
        for (int j = k >> 1; j > 0; j >>= 1) {
            u64 o = shfl_xor64(v, j);
            bool takeMin = (((lane & j) == 0) == ((lane & k) == 0));
            if ((o < v) == takeMin) v = o;
        }
    }
}

// bitonic merge (input bitonic), ascending by lane
__device__ __forceinline__ void bitonic_merge32(u64& v, int lane) {
#pragma unroll
    for (int j = 16; j > 0; j >>= 1) {
        u64 o = shfl_xor64(v, j);
        bool takeMin = ((lane & j) == 0);
        if ((o < v) == takeMin) v = o;
    }
}

// insert key k into sorted-ascending L (drops old max). No-op if k >= L[31].
__device__ __forceinline__ void warp_insert(u64& L, u64 k, int lane) {
    unsigned mlt = __ballot_sync(FULLMASK, L < k);
    int p = __popc(mlt);
    u64 Ls = __shfl_up_sync(FULLMASK, L, 1);
    if (lane >= p) L = (lane == p) ? k : Ls;
}

__global__ void __launch_bounds__(128)
radius_graph_kernel(const float* __restrict__ pos,
                    const int* __restrict__ batch,
                    float* __restrict__ out,
                    int N) {
    __shared__ u64 spriv[4][PDEPTH][32];   // [warp][slot][lane] lane-private
    __shared__ u64 scomp[4][COMPCAP];      // compacted keys (+pad)

    const int wb = (int)(threadIdx.x >> 5);
    const int i = (int)((blockIdx.x * blockDim.x + threadIdx.x) >> 5);
    const int lane = threadIdx.x & 31;
    if (i >= N) return;
    const int nk = N * KNB;
    const float D2T = __uint_as_float(D2_THRESH_BITS);

    // pad compacted buffer with INVALID (chunk reads rely on it)
#pragma unroll
    for (int s = 0; s < COMPCAP / 32; s++) scomp[wb][s * 32 + lane] = INVALID_KEY;

    const float xi = pos[3 * i + 0], yi = pos[3 * i + 1], zi = pos[3 * i + 2];
    const float sqi = sumsq_xla(xi, yi, zi);
    const int b = batch[i];

    const int2 bounds = warp_bound_dual(batch, N, b, lane);
    const int LO = bounds.x, HI = bounds.y;
    const int per = (HI - LO + 31) >> 5;

    u64 L = INVALID_KEY;
    int total = 0;

    if (per <= PDEPTH) {
        // ── fast path: lane-private buffering, NO warp-sync ops in the loop ──
        int cnt = 0;
        for (int t = 0; t < per; t++) {
            int j = LO + lane + (t << 5);
            if (j < HI && j != i) {
                float xj = pos[3 * j + 0];
                float yj = pos[3 * j + 1];
                float zj = pos[3 * j + 2];
                float sqj = sumsq_xla(xj, yj, zj);
                float dot = __fmaf_rn(zi, zj, __fmaf_rn(yi, yj, __fmul_rn(xi, xj)));
                float d2 = __fsub_rn(__fadd_rn(sqi, sqj), __fmul_rn(2.0f, dot));
                if (d2 <= D2T) {   // exact equivalent of dist<=5.0
                    float dist = __fsqrt_rn(fmaxf(d2, 0.0f));
                    u64 key = (((u64)__float_as_uint(dist)) << 32) | (unsigned int)j;
                    spriv[wb][cnt][lane] = key;
                    cnt++;
                }
            }
        }
        __syncwarp();   // orders private stores + scomp init vs compaction writes

        // warp prefix scan of counts -> dense destinations (order irrelevant:
        // keys are distinct and fully sorted below)
        int c = cnt;
#pragma unroll
        for (int d = 1; d < 32; d <<= 1) {
            int n = __shfl_up_sync(FULLMASK, c, d);
            if (lane >= d) c += n;
        }
        const int ex = c - cnt;
        total = __shfl_sync(FULLMASK, c, 31);
        for (int s = 0; s < cnt; s++) scomp[wb][ex + s] = spriv[wb][s][lane];
        __syncwarp();
    } else {
        // ── fallback (molecule > 256 atoms): ballot-compaction into scomp ──
        const unsigned lmlt = (1u << lane) - 1u;
        int cnt = 0;
        bool first = true;
        for (int t = 0; t < per; t++) {
            int j = LO + lane + (t << 5);
            u64 key = INVALID_KEY;
            if (j < HI && j != i) {
                float xj = pos[3 * j + 0];
                float yj = pos[3 * j + 1];
                float zj = pos[3 * j + 2];
                float sqj = sumsq_xla(xj, yj, zj);
                float dot = __fmaf_rn(zi, zj, __fmaf_rn(yi, yj, __fmul_rn(xi, xj)));
                float d2 = __fsub_rn(__fadd_rn(sqi, sqj), __fmul_rn(2.0f, dot));
                if (d2 <= D2T) {
                    float dist = __fsqrt_rn(fmaxf(d2, 0.0f));
                    key = (((u64)__float_as_uint(dist)) << 32) | (unsigned int)j;
                }
            }
            unsigned bal = __ballot_sync(FULLMASK, key != INVALID_KEY);
            if (bal) {
                int nv = __popc(bal);
                if (cnt + nv > 64) {
                    // fold buffer into L, reset
                    __syncwarp();
                    u64 A = scomp[wb][lane];
                    u64 B = scomp[wb][32 + lane];
                    bitonic_sort32(A, lane);
                    bitonic_sort32(B, lane);
                    u64 brev = shfl_xor64(B, 31);
                    u64 C = (A < brev) ? A : brev;
                    bitonic_merge32(C, lane);
                    if (first) { L = C; first = false; }
                    else {
                        u64 crev = shfl_xor64(C, 31);
                        L = (L < crev) ? L : crev;
                        bitonic_merge32(L, lane);
                    }
                    scomp[wb][lane] = INVALID_KEY;
                    scomp[wb][32 + lane] = INVALID_KEY;
                    __syncwarp();
                    cnt = 0;
                }
                int r = __popc(bal & lmlt);
                if (key != INVALID_KEY) scomp[wb][cnt + r] = key;
                cnt += nv;
            }
        }
        __syncwarp();
        if (!first) {
            // merge remaining buffer into existing L
            if (cnt > 0) {
                u64 A = scomp[wb][lane];
                bitonic_sort32(A, lane);
                u64 arev = shfl_xor64(A, 31);
                L = (L < arev) ? L : arev;
                bitonic_merge32(L, lane);
                if (cnt > 32) {
                    u64 B = scomp[wb][32 + lane];
                    bitonic_sort32(B, lane);
                    u64 brev = shfl_xor64(B, 31);
                    L = (L < brev) ? L : brev;
                    bitonic_merge32(L, lane);
                }
            }
            total = -1;   // signal: L already final
        } else {
            total = cnt;  // shared finalize below
        }
    }

    // ── shared finalize: build sorted top-32 from scomp[0..total) ──
    if (total > 0) {
        u64 A = scomp[wb][lane];
        bitonic_sort32(A, lane);
        L = A;
        int done = 32;
        while (done < total) {
            int rem = total - done;
            if (rem <= 16) {
                for (int idx = 0; idx < rem; idx++)
                    warp_insert(L, scomp[wb][done + idx], lane);
                done = total;
            } else {
                u64 B = scomp[wb][done + lane];   // padded INVALID beyond total
                bitonic_sort32(B, lane);
                u64 brev = shfl_xor64(B, 31);
                L = (L < brev) ? L : brev;
                bitonic_merge32(L, lane);
                done += 32;
            }
        }
    }

    // lane k owns output slot k: k-th nearest neighbor (exact top_k order)
    const bool valid = (L != INVALID_KEY);
    const int jd = valid ? (int)(unsigned int)(L & 0xFFFFFFFFull) : i;
    const int e = i * KNB + lane;
    float vx = 0.0f, vy = 0.0f, vz = 0.0f;
    if (valid) {
        vx = __fsub_rn(pos[3 * jd + 0], xi);
        vy = __fsub_rn(pos[3 * jd + 1], yi);
        vz = __fsub_rn(pos[3 * jd + 2], zi);
    }
    out[e]                  = (float)i;            // src
    out[nk + e]             = (float)jd;           // dst
    out[2 * nk + 3 * e + 0] = vx;                  // edge_vec
    out[2 * nk + 3 * e + 1] = vy;
    out[2 * nk + 3 * e + 2] = vz;
    out[5 * nk + e]         = valid ? 1.0f : 0.0f; // mask
}

extern "C" void kernel_launch(void* const* d_in, const int* in_sizes, int n_in,
                              void* d_out, int out_size) {
    const float* pos = (const float*)d_in[0];
    const int* batch = (const int*)d_in[1];
    float* out = (float*)d_out;
    int N = in_sizes[1];            // batch has one entry per atom
    (void)n_in; (void)out_size;

    const int warpsPerBlock = 4;    // 128 threads; one atom per warp
    int blocks = (N + warpsPerBlock - 1) / warpsPerBlock;
    radius_graph_kernel<<<blocks, warpsPerBlock * 32>>>(pos, batch, out, N);
}

// round 16
// speedup vs baseline: 1.1165x; 1.0021x over previous
#include <cuda_runtime.h>
#include <cuda_bf16.h>

#define KNB 32
#define INVALID_KEY 0xFFFFFFFFFFFFFFFFull
#define FULLMASK 0xFFFFFFFFu
// exact d2 threshold: dist<=5.0 with dist=__fsqrt_rn(d2)  <=>  d2 <= 25+2^-19
#define D2_THRESH_BITS 0x41C80001u

typedef unsigned long long u64;

// XLA-matching sum of squares: rn(rn(rn(x^2)+rn(y^2))+rn(z^2)), NO fma fusion
__device__ __forceinline__ float sumsq_xla(float x, float y, float z) {
    return __fadd_rn(__fadd_rn(__fmul_rn(x, x), __fmul_rn(y, y)), __fmul_rn(z, z));
}

__device__ __forceinline__ u64 shfl_xor64(u64 v, int m) { return __shfl_xor_sync(FULLMASK, v, m); }

// dual warp-parallel 32-ary search over the SAME molecule id b:
//   LO = first idx with batch[idx] >= b ; HI = first idx with batch[idx] > b
__device__ __forceinline__ int2 warp_bound_dual(const int* __restrict__ batch, int N,
                                                int b, int lane) {
    int l0 = 0, w0 = N, l1 = 0, w1 = N;
    while (w0 > 0 || w1 > 0) {
        int step0 = (w0 + 31) >> 5;
        int step1 = (w1 + 31) >> 5;
        int off0 = lane * step0;
        int off1 = lane * step1;
        bool in0 = (w0 > 0) && (off0 < w0);
        bool in1 = (w1 > 0) && (off1 < w1);
        int m0 = l0 + (in0 ? off0 : 0);
        int m1 = l1 + (in1 ? off1 : 0);
        int v0 = batch[m0];          // both probes in flight together
        int v1 = batch[m1];
        unsigned bal0 = __ballot_sync(FULLMASK, in0 && (v0 < b));
        unsigned bal1 = __ballot_sync(FULLMASK, in1 && (v1 <= b));
        if (w0 > 0) {
            int c = __popc(bal0);
            if (c == 0) w0 = 0;
            else {
                int newl = l0 + (c - 1) * step0 + 1;
                int ub = (c * step0 < w0) ? (l0 + c * step0) : (l0 + w0);
                w0 = ub - newl; l0 = newl;
            }
        }
        if (w1 > 0) {
            int c = __popc(bal1);
            if (c == 0) w1 = 0;
            else {
                int newl = l1 + (c - 1) * step1 + 1;
                int ub = (c * step1 < w1) ? (l1 + c * step1) : (l1 + w1);
                w1 = ub - newl; l1 = newl;
            }
        }
    }
    return make_int2(l0, l1);
}

// full bitonic sort of 32 keys, ascending by lane
__device__ __forceinline__ void bitonic_sort32(u64& v, int lane) {
#pragma unroll
    for (int k = 2; k <= 32; k <<= 1) {
#pragma unroll
        for (int j = k >> 1; j > 0; j >>= 1) {
            u64 o = shfl_xor64(v, j);
            bool takeMin = (((lane & j) == 0) == ((lane & k) == 0));
            if ((o < v) == takeMin) v = o;
        }
    }
}

// two independent sorts interleaved (2x ILP on the shfl chain)
__device__ __forceinline__ void bitonic_sort32_pair(u64& a, u64& b, int lane) {
#pragma unroll
    for (int k = 2; k <= 32; k <<= 1) {
#pragma unroll
        for (int j = k >> 1; j > 0; j >>= 1) {
            u64 oa = shfl_xor64(a, j);
            u64 ob = shfl_xor64(b, j);
            bool takeMin = (((lane & j) == 0) == ((lane & k) == 0));
            if ((oa < a) == takeMin) a = oa;
            if ((ob < b) == takeMin) b = ob;
        }
    }
}

// bitonic merge (input bitonic), ascending by lane
__device__ __forceinline__ void bitonic_merge32(u64& v, int lane) {
#pragma unroll
    for (int j = 16; j > 0; j >>= 1) {
        u64 o = shfl_xor64(v, j);
        bool takeMin = ((lane & j) == 0);
        if ((o < v) == takeMin) v = o;
    }
}

// insert key k into sorted-ascending L (drops old max). No-op if k >= L[31].
__device__ __forceinline__ void warp_insert(u64& L, u64 k, int lane) {
    unsigned mlt = __ballot_sync(FULLMASK, L < k);
    int p = __popc(mlt);
    u64 Ls = __shfl_up_sync(FULLMASK, L, 1);
    if (lane >= p) L = (lane == p) ? k : Ls;
}

// rare mid-loop flush: fold the 64-slot smem buffer into L, reset buffer
__device__ __forceinline__ void flush_smem(u64& L, bool& first, int& cnt,
                                           u64* buf, int lane) {
    __syncwarp();
    u64 A = buf[lane];
    u64 B = buf[32 + lane];
    bitonic_sort32_pair(A, B, lane);
    u64 brev = shfl_xor64(B, 31);
    u64 C = (A < brev) ? A : brev;
    bitonic_merge32(C, lane);              // top-32 of the 64 slots
    if (first) { L = C; first = false; }
    else {
        u64 crev = shfl_xor64(C, 31);
        L = (L < crev) ? L : crev;
        bitonic_merge32(L, lane);
    }
    buf[lane] = INVALID_KEY;
    buf[32 + lane] = INVALID_KEY;
    __syncwarp();
    cnt = 0;
}

// rare final path when a mid-loop flush happened: merge remaining buffer into L
__device__ __forceinline__ void finalize_merge(u64& L, int cnt, u64 A,
                                               const u64* buf, int lane) {
    if (cnt == 0) return;
    u64 arev = shfl_xor64(A, 31);
    L = (L < arev) ? L : arev;
    bitonic_merge32(L, lane);
    if (cnt > 32) {
        u64 B = buf[32 + lane];
        bitonic_sort32(B, lane);
        u64 brev = shfl_xor64(B, 31);
        L = (L < brev) ? L : brev;
        bitonic_merge32(L, lane);
    }
}

// scatter one ballot's candidates into the 64-slot buffer (cnt-dense)
__device__ __forceinline__ void scatter(u64& L, bool& first, int& cnt, u64* buf,
                                        u64 key, unsigned bal, unsigned lmlt, int lane) {
    int nv = __popc(bal);
    if (cnt + nv > 64) flush_smem(L, first, cnt, buf, lane);
    int r = __popc(bal & lmlt);
    if (key != INVALID_KEY) buf[cnt + r] = key;
    cnt += nv;
}

__global__ void __launch_bounds__(128)
radius_graph_kernel(const float* __restrict__ pos,
                    const int* __restrict__ batch,
                    float* __restrict__ out,
                    int N) {
    __shared__ u64 sbuf[4][64];
    const int wb = (int)(threadIdx.x >> 5);
    const int i = (int)((blockIdx.x * blockDim.x + threadIdx.x) >> 5);
    const int lane = threadIdx.x & 31;
    if (i >= N) return;
    const int nk = N * KNB;
    const float D2T = __uint_as_float(D2_THRESH_BITS);
    const unsigned lmlt = (1u << lane) - 1u;

    sbuf[wb][lane] = INVALID_KEY;
    sbuf[wb][32 + lane] = INVALID_KEY;
    __syncwarp();

    const float xi = pos[3 * i + 0], yi = pos[3 * i + 1], zi = pos[3 * i + 2];
    const float sqi = sumsq_xla(xi, yi, zi);
    const int b = batch[i];

    const int2 bounds = warp_bound_dual(batch, N, b, lane);
    const int LO = bounds.x, HI = bounds.y;

    u64 L = INVALID_KEY;
    int cnt = 0;
    bool first = true;

    const int nf = (HI - LO) >> 5;    // guaranteed-full 32-candidate batches
    int t = 0;

    // ── paired full batches: 6 loads in flight before any ballot ──
    for (; t + 1 < nf; t += 2) {
        const int ja = LO + lane + (t << 5);
        const int jb = ja + 32;
        const float xa = pos[3 * ja + 0], ya = pos[3 * ja + 1], za = pos[3 * ja + 2];
        const float xb = pos[3 * jb + 0], yb = pos[3 * jb + 1], zb = pos[3 * jb + 2];

        u64 ka = INVALID_KEY, kb = INVALID_KEY;
        {
            float sqj = sumsq_xla(xa, ya, za);
            float dot = __fmaf_rn(zi, za, __fmaf_rn(yi, ya, __fmul_rn(xi, xa)));
            float d2 = __fsub_rn(__fadd_rn(sqi, sqj), __fmul_rn(2.0f, dot));
            if (d2 <= D2T && ja != i) {
                float dist = __fsqrt_rn(fmaxf(d2, 0.0f));
                ka = (((u64)__float_as_uint(dist)) << 32) | (unsigned int)ja;
            }
        }
        {
            float sqj = sumsq_xla(xb, yb, zb);
            float dot = __fmaf_rn(zi, zb, __fmaf_rn(yi, yb, __fmul_rn(xi, xb)));
            float d2 = __fsub_rn(__fadd_rn(sqi, sqj), __fmul_rn(2.0f, dot));
            if (d2 <= D2T && jb != i) {
                float dist = __fsqrt_rn(fmaxf(d2, 0.0f));
                kb = (((u64)__float_as_uint(dist)) << 32) | (unsigned int)jb;
            }
        }
        unsigned bala = __ballot_sync(FULLMASK, ka != INVALID_KEY);
        unsigned balb = __ballot_sync(FULLMASK, kb != INVALID_KEY);
        if (bala) scatter(L, first, cnt, &sbuf[wb][0], ka, bala, lmlt, lane);
        if (balb) scatter(L, first, cnt, &sbuf[wb][0], kb, balb, lmlt, lane);
    }
    // ── leftover single full batch ──
    for (; t < nf; t++) {
        const int j = LO + lane + (t << 5);
        const float xj = pos[3 * j + 0], yj = pos[3 * j + 1], zj = pos[3 * j + 2];
        u64 key = INVALID_KEY;
        float sqj = sumsq_xla(xj, yj, zj);
        float dot = __fmaf_rn(zi, zj, __fmaf_rn(yi, yj, __fmul_rn(xi, xj)));
        float d2 = __fsub_rn(__fadd_rn(sqi, sqj), __fmul_rn(2.0f, dot));
        if (d2 <= D2T && j != i) {
            float dist = __fsqrt_rn(fmaxf(d2, 0.0f));
            key = (((u64)__float_as_uint(dist)) << 32) | (unsigned int)j;
        }
        unsigned bal = __ballot_sync(FULLMASK, key != INVALID_KEY);
        if (bal) scatter(L, first, cnt, &sbuf[wb][0], key, bal, lmlt, lane);
    }
    // ── tail batch (the only place needing the range guard) ──
    {
        const int j = LO + lane + (nf << 5);
        u64 key = INVALID_KEY;
        if (j < HI && j != i) {
            float xj = pos[3 * j + 0], yj = pos[3 * j + 1], zj = pos[3 * j + 2];
            float sqj = sumsq_xla(xj, yj, zj);
            float dot = __fmaf_rn(zi, zj, __fmaf_rn(yi, yj, __fmul_rn(xi, xj)));
            float d2 = __fsub_rn(__fadd_rn(sqi, sqj), __fmul_rn(2.0f, dot));
            if (d2 <= D2T) {
                float dist = __fsqrt_rn(fmaxf(d2, 0.0f));
                key = (((u64)__float_as_uint(dist)) << 32) | (unsigned int)j;
            }
        }
        unsigned bal = __ballot_sync(FULLMASK, key != INVALID_KEY);
        if (bal) scatter(L, first, cnt, &sbuf[wb][0], key, bal, lmlt, lane);
    }

    __syncwarp();
    u64 A = sbuf[wb][lane];
    bitonic_sort32(A, lane);

    if (first) {
        // dominant path: no mid-loop flush happened
        if (cnt > 0) L = A;
        int m = cnt > 32 ? cnt - 32 : 0;
        for (int idx = 0; idx < m; idx++)
            warp_insert(L, sbuf[wb][32 + idx], lane);
    } else {
        finalize_merge(L, cnt, A, &sbuf[wb][0], lane);
    }

    // lane k owns output slot k: k-th nearest neighbor (exact top_k order)
    const bool valid = (L != INVALID_KEY);
    const int jd = valid ? (int)(unsigned int)(L & 0xFFFFFFFFull) : i;
    const int e = i * KNB + lane;
    float vx = 0.0f, vy = 0.0f, vz = 0.0f;
    if (valid) {
        vx = __fsub_rn(pos[3 * jd + 0], xi);
        vy = __fsub_rn(pos[3 * jd + 1], yi);
        vz = __fsub_rn(pos[3 * jd + 2], zi);
    }
    out[e]                  = (float)i;            // src
    out[nk + e]             = (float)jd;           // dst
    out[2 * nk + 3 * e + 0] = vx;                  // edge_vec
    out[2 * nk + 3 * e + 1] = vy;
    out[2 * nk + 3 * e + 2] = vz;
    out[5 * nk + e]         = valid ? 1.0f : 0.0f; // mask
}

extern "C" void kernel_launch(void* const* d_in, const int* in_sizes, int n_in,
                              void* d_out, int out_size) {
    const float* pos = (const float*)d_in[0];
    const int* batch = (const int*)d_in[1];
    float* out = (float*)d_out;
    int N = in_sizes[1];            // batch has one entry per atom
    (void)n_in; (void)out_size;

    const int warpsPerBlock = 4;    // 128 threads; one atom per warp
    int blocks = (N + warpsPerBlock - 1) / warpsPerBlock;
    radius_graph_kernel<<<blocks, warpsPerBlock * 32>>>(pos, batch, out, N);
}

// round 17
// speedup vs baseline: 1.1382x; 1.0194x over previous
#include <cuda_runtime.h>
#include <cuda_bf16.h>

#define KNB 32
#define INVALID_KEY 0xFFFFFFFFFFFFFFFFull
#define FULLMASK 0xFFFFFFFFu
// exact d2 threshold: dist<=5.0 with dist=__fsqrt_rn(d2)  <=>  d2 <= 25+2^-19
#define D2_THRESH_BITS 0x41C80001u
#define WIN 512   // bound-search window half-width (molecules are ~128 atoms)

typedef unsigned long long u64;

// XLA-matching sum of squares: rn(rn(rn(x^2)+rn(y^2))+rn(z^2)), NO fma fusion
__device__ __forceinline__ float sumsq_xla(float x, float y, float z) {
    return __fadd_rn(__fadd_rn(__fmul_rn(x, x), __fmul_rn(y, y)), __fmul_rn(z, z));
}

__device__ __forceinline__ u64 shfl_xor64(u64 v, int m) { return __shfl_xor_sync(FULLMASK, v, m); }

// dual warp-parallel 32-ary search over given sub-ranges:
//   LO: first idx in [l0, l0+w0) with batch[idx] >= b
//   HI: first idx in [l1, l1+w1) with batch[idx] > b
__device__ __forceinline__ int2 warp_bound_dual_range(const int* __restrict__ batch,
                                                      int b, int lane,
                                                      int l0, int w0, int l1, int w1) {
    while (w0 > 0 || w1 > 0) {
        int step0 = (w0 + 31) >> 5;
        int step1 = (w1 + 31) >> 5;
        int off0 = lane * step0;
        int off1 = lane * step1;
        bool in0 = (w0 > 0) && (off0 < w0);
        bool in1 = (w1 > 0) && (off1 < w1);
        int m0 = l0 + (in0 ? off0 : 0);
        int m1 = l1 + (in1 ? off1 : 0);
        int v0 = batch[m0];          // both probes in flight together
        int v1 = batch[m1];
        unsigned bal0 = __ballot_sync(FULLMASK, in0 && (v0 < b));
        unsigned bal1 = __ballot_sync(FULLMASK, in1 && (v1 <= b));
        if (w0 > 0) {
            int c = __popc(bal0);
            if (c == 0) w0 = 0;
            else {
                int newl = l0 + (c - 1) * step0 + 1;
                int ub = (c * step0 < w0) ? (l0 + c * step0) : (l0 + w0);
                w0 = ub - newl; l0 = newl;
            }
        }
        if (w1 > 0) {
            int c = __popc(bal1);
            if (c == 0) w1 = 0;
            else {
                int newl = l1 + (c - 1) * step1 + 1;
                int ub = (c * step1 < w1) ? (l1 + c * step1) : (l1 + w1);
                w1 = ub - newl; l1 = newl;
            }
        }
    }
    return make_int2(l0, l1);
}

// windowed bound search around i (batch[i]==b guarantees LO<=i<=HI).
// Window-edge results are verified; overflow falls back to full range (exact).
__device__ __forceinline__ int2 warp_bound_windowed(const int* __restrict__ batch,
                                                    int N, int b, int i, int lane) {
    int ls = i - WIN; if (ls < 0) ls = 0;
    int he = i + WIN + 1; if (he > N) he = N;
    int2 r = warp_bound_dual_range(batch, b, lane, ls, i + 1 - ls, i, he - i);
    bool ok0 = (r.x > ls) || (ls == 0);
    if (!ok0) ok0 = (batch[ls - 1] < b);        // broadcast load, warp-uniform
    bool ok1 = (r.y < he) || (he == N);
    if (!ok1) ok1 = (batch[he] > b);            // note: r.y==he means unresolved
    if (ok0 && ok1) return r;
    return warp_bound_dual_range(batch, b, lane, 0, N, 0, N);   // rare exact fallback
}

// full bitonic sort of 32 keys, ascending by lane
__device__ __forceinline__ void bitonic_sort32(u64& v, int lane) {
#pragma unroll
    for (int k = 2; k <= 32; k <<= 1) {
#pragma unroll
        for (int j = k >> 1; j > 0; j >>= 1) {
            u64 o = shfl_xor64(v, j);
            bool takeMin = (((lane & j) == 0) == ((lane & k) == 0));
            if ((o < v) == takeMin) v = o;
        }
    }
}

// two independent sorts interleaved (2x ILP on the shfl chain)
__device__ __forceinline__ void bitonic_sort32_pair(u64& a, u64& b, int lane) {
#pragma unroll
    for (int k = 2; k <= 32; k <<= 1) {
#pragma unroll
        for (int j = k >> 1; j > 0; j >>= 1) {
            u64 oa = shfl_xor64(a, j);
            u64 ob = shfl_xor64(b, j);
            bool takeMin = (((lane & j) == 0) == ((lane & k) == 0));
            if ((oa < a) == takeMin) a = oa;
            if ((ob < b) == takeMin) b = ob;
        }
    }
}

// bitonic merge (input bitonic), ascending by lane
__device__ __forceinline__ void bitonic_merge32(u64& v, int lane) {
#pragma unroll
    for (int j = 16; j > 0; j >>= 1) {
        u64 o = shfl_xor64(v, j);
        bool takeMin = ((lane & j) == 0);
        if ((o < v) == takeMin) v = o;
    }
}

// insert key k into sorted-ascending L (drops old max). No-op if k >= L[31].
__device__ __forceinline__ void warp_insert(u64& L, u64 k, int lane) {
    unsigned mlt = __ballot_sync(FULLMASK, L < k);
    int p = __popc(mlt);
    u64 Ls = __shfl_up_sync(FULLMASK, L, 1);
    if (lane >= p) L = (lane == p) ? k : Ls;
}

// rare mid-loop flush: fold the 64-slot smem buffer into L, reset buffer
__device__ __forceinline__ void flush_smem(u64& L, bool& first, int& cnt,
                                           u64* buf, int lane) {
    __syncwarp();
    u64 A = buf[lane];
    u64 B = buf[32 + lane];
    bitonic_sort32_pair(A, B, lane);
    u64 brev = shfl_xor64(B, 31);
    u64 C = (A < brev) ? A : brev;
    bitonic_merge32(C, lane);              // top-32 of the 64 slots
    if (first) { L = C; first = false; }
    else {
        u64 crev = shfl_xor64(C, 31);
        L = (L < crev) ? L : crev;
        bitonic_merge32(L, lane);
    }
    buf[lane] = INVALID_KEY;
    buf[32 + lane] = INVALID_KEY;
    __syncwarp();
    cnt = 0;
}

// rare final path when a mid-loop flush happened: merge remaining buffer into L
__device__ __forceinline__ void finalize_merge(u64& L, int cnt, u64 A,
                                               const u64* buf, int lane) {
    if (cnt == 0) return;
    u64 arev = shfl_xor64(A, 31);
    L = (L < arev) ? L : arev;
    bitonic_merge32(L, lane);
    if (cnt > 32) {
        u64 B = buf[32 + lane];
        bitonic_sort32(B, lane);
        u64 brev = shfl_xor64(B, 31);
        L = (L < brev) ? L : brev;
        bitonic_merge32(L, lane);
    }
}

__global__ void __launch_bounds__(128)
radius_graph_kernel(const float* __restrict__ pos,
                    const int* __restrict__ batch,
                    float* __restrict__ out,
                    int N) {
    __shared__ u64 sbuf[4][64];
    const int wb = (int)(threadIdx.x >> 5);
    const int i = (int)((blockIdx.x * blockDim.x + threadIdx.x) >> 5);
    const int lane = threadIdx.x & 31;
    if (i >= N) return;
    const int nk = N * KNB;
    const float D2T = __uint_as_float(D2_THRESH_BITS);
    const unsigned lmlt = (1u << lane) - 1u;

    sbuf[wb][lane] = INVALID_KEY;
    sbuf[wb][32 + lane] = INVALID_KEY;
    __syncwarp();

    const float xi = pos[3 * i + 0], yi = pos[3 * i + 1], zi = pos[3 * i + 2];
    const float sqi = sumsq_xla(xi, yi, zi);
    const int b = batch[i];

    const int2 bounds = warp_bound_windowed(batch, N, b, i, lane);
    const int LO = bounds.x, HI = bounds.y;

    u64 L = INVALID_KEY;
    int cnt = 0;
    bool first = true;

    const int per = (HI - LO + 31) >> 5;
    for (int t = 0; t < per; t++) {
        int j = LO + lane + (t << 5);
        u64 key = INVALID_KEY;
        if (j < HI && j != i) {
            float xj = pos[3 * j + 0];
            float yj = pos[3 * j + 1];
            float zj = pos[3 * j + 2];
            float sqj = sumsq_xla(xj, yj, zj);
            float dot = __fmaf_rn(zi, zj, __fmaf_rn(yi, yj, __fmul_rn(xi, xj)));
            float d2 = __fsub_rn(__fadd_rn(sqi, sqj), __fmul_rn(2.0f, dot));
            if (d2 <= D2T) {   // exact equivalent of dist<=5.0
                float dist = __fsqrt_rn(fmaxf(d2, 0.0f));
                key = (((u64)__float_as_uint(dist)) << 32) | (unsigned int)j;
            }
        }
        unsigned bal = __ballot_sync(FULLMASK, key != INVALID_KEY);
        if (bal) {
            int nv = __popc(bal);
            if (cnt + nv > 64) flush_smem(L, first, cnt, &sbuf[wb][0], lane);
            int r = __popc(bal & lmlt);
            if (key != INVALID_KEY) sbuf[wb][cnt + r] = key;
            cnt += nv;
        }
    }

    __syncwarp();
    u64 A = sbuf[wb][lane];
    bitonic_sort32(A, lane);

    if (first) {
        // dominant path: no mid-loop flush happened
        if (cnt > 0) L = A;
        int m = cnt > 32 ? cnt - 32 : 0;
        for (int idx = 0; idx < m; idx++)
            warp_insert(L, sbuf[wb][32 + idx], lane);
    } else {
        finalize_merge(L, cnt, A, &sbuf[wb][0], lane);
    }

    // lane k owns output slot k: k-th nearest neighbor (exact top_k order)
    const bool valid = (L != INVALID_KEY);
    const int jd = valid ? (int)(unsigned int)(L & 0xFFFFFFFFull) : i;
    const int e = i * KNB + lane;
    float vx = 0.0f, vy = 0.0f, vz = 0.0f;
    if (valid) {
        vx = __fsub_rn(pos[3 * jd + 0], xi);
        vy = __fsub_rn(pos[3 * jd + 1], yi);
        vz = __fsub_rn(pos[3 * jd + 2], zi);
    }
    out[e]                  = (float)i;            // src
    out[nk + e]             = (float)jd;           // dst
    out[2 * nk + 3 * e + 0] = vx;                  // edge_vec
    out[2 * nk + 3 * e + 1] = vy;
    out[2 * nk + 3 * e + 2] = vz;
    out[5 * nk + e]         = valid ? 1.0f : 0.0f; // mask
}

extern "C" void kernel_launch(void* const* d_in, const int* in_sizes, int n_in,
                              void* d_out, int out_size) {
    const float* pos = (const float*)d_in[0];
    const int* batch = (const int*)d_in[1];
    float* out = (float*)d_out;
    int N = in_sizes[1];            // batch has one entry per atom
    (void)n_in; (void)out_size;

    const int warpsPerBlock = 4;    // 128 threads; one atom per warp
    int blocks = (N + warpsPerBlock - 1) / warpsPerBlock;
    radius_graph_kernel<<<blocks, warpsPerBlock * 32>>>(pos, batch, out, N);
}